// round 5
// baseline (speedup 1.0000x reference)
#include <cuda_runtime.h>

#define NNODES 10000
#define NEDGES 160000
#define CINCH  32
#define H      64
#define T      12
#define OUTC   12
#define KW     3
#define FEAT   (H * T)  // 768

typedef unsigned long long ull;

// ---------------- device scratch (no allocations allowed) ----------------
__device__ float g_bufA[NNODES * FEAT];
__device__ float g_bufB[NNODES * FEAT];
__device__ float g_dis[NNODES];               // deg accumulator, then rsqrt(deg)
// tconv weights: [c][o(128)][k pad to 4]; pad slot stays 0 (static zero-init, never written)
__device__ float g_wt1a[CINCH * 2 * H * 4];
__device__ float g_wt1b[H * 2 * H * 4];
__device__ float g_wt2a[H * 2 * H * 4];
__device__ float g_wt2b[H * 2 * H * 4];
__device__ ull   g_gc1T[H * H];               // dup-packed {w,w}, [c*64 + o]
__device__ ull   g_gc2T[H * H];
// CSR
__device__ int   g_cnt[NNODES];
__device__ int   g_fill[NNODES];
__device__ int   g_row[NNODES + 1];
__device__ int   g_col[NEDGES];
__device__ float g_nrm[NEDGES];

// ---------------- f32x2 helpers ----------------
#define FMA2(a, x, y) asm("fma.rn.f32x2 %0, %1, %2, %0;" : "+l"(a) : "l"(x), "l"(y))
__device__ __forceinline__ float lof(ull v) { return __uint_as_float((unsigned)(v & 0xffffffffull)); }
__device__ __forceinline__ float hif(ull v) { return __uint_as_float((unsigned)(v >> 32)); }
__device__ __forceinline__ ull dupr(float f) {
    ull r;
    asm("mov.b64 %0, {%1, %1};" : "=l"(r) : "f"(f));
    return r;
}
__device__ __forceinline__ ull dup2h(float f) {
    unsigned u = __float_as_uint(f);
    return ((ull)u << 32) | (ull)u;
}

// ---------------- fused prep: 4 weight transposes + 2 gcn transposes + deg init ----------
__device__ __forceinline__ void tw_one(const float* __restrict__ w, float* __restrict__ wT,
                                       int cin, int idx) {
    int o = idx / (cin * KW);
    int r = idx - o * cin * KW;
    int c = r / KW;
    int k = r - c * KW;
    wT[(c * 128 + o) * 4 + k] = w[idx];
}

__global__ void k_prep(const float* __restrict__ w1a, const float* __restrict__ w1b,
                       const float* __restrict__ w2a, const float* __restrict__ w2b,
                       const float* __restrict__ gc1, const float* __restrict__ gc2) {
    int idx = blockIdx.x * blockDim.x + threadIdx.x;
    if (idx < 12288) { tw_one(w1a, g_wt1a, CINCH, idx); return; }
    idx -= 12288;
    if (idx < 24576) { tw_one(w1b, g_wt1b, H, idx); return; }
    idx -= 24576;
    if (idx < 24576) { tw_one(w2a, g_wt2a, H, idx); return; }
    idx -= 24576;
    if (idx < 24576) { tw_one(w2b, g_wt2b, H, idx); return; }
    idx -= 24576;
    if (idx < 4096) { int o = idx / H, c = idx - o * H; g_gc1T[c * H + o] = dup2h(gc1[idx]); return; }
    idx -= 4096;
    if (idx < 4096) { int o = idx / H, c = idx - o * H; g_gc2T[c * H + o] = dup2h(gc2[idx]); return; }
    idx -= 4096;
    if (idx < NNODES) { g_dis[idx] = 1.0f; g_cnt[idx] = 0; }
}

__global__ void k_deg_acc(const int* __restrict__ dst, const float* __restrict__ ew) {
    int e = blockIdx.x * blockDim.x + threadIdx.x;
    if (e < NEDGES) {
        int d = dst[e];
        atomicAdd(&g_dis[d], ew[e]);
        atomicAdd(&g_cnt[d], 1);
    }
}

// rsqrt + single-block exclusive scan (warp-shuffle based)
__global__ void k_scan() {
    __shared__ int wsum[32];
    __shared__ int carry_s;
    int tid = threadIdx.x;  // 1024
    int lane = tid & 31, wid = tid >> 5;
    for (int i = tid; i < NNODES; i += 1024) g_dis[i] = rsqrtf(g_dis[i]);
    if (tid == 0) carry_s = 0;
    __syncthreads();
    for (int base = 0; base < NNODES; base += 1024) {
        int i = base + tid;
        int v = (i < NNODES) ? g_cnt[i] : 0;
        int s = v;
#pragma unroll
        for (int off = 1; off < 32; off <<= 1) {
            int t = __shfl_up_sync(0xffffffffu, s, off);
            if (lane >= off) s += t;
        }
        if (lane == 31) wsum[wid] = s;
        __syncthreads();
        if (wid == 0) {
            int ws = wsum[lane];
#pragma unroll
            for (int off = 1; off < 32; off <<= 1) {
                int t = __shfl_up_sync(0xffffffffu, ws, off);
                if (lane >= off) ws += t;
            }
            wsum[lane] = ws;
        }
        __syncthreads();
        int prefix = carry_s + (wid ? wsum[wid - 1] : 0) + s - v;  // exclusive
        if (i < NNODES) { g_row[i] = prefix; g_fill[i] = 0; }
        __syncthreads();
        if (tid == 1023) carry_s += wsum[31];
        __syncthreads();
    }
    if (tid == 0) g_row[NNODES] = carry_s;
}

__global__ void k_fill(const int* __restrict__ src, const int* __restrict__ dst,
                       const float* __restrict__ ew) {
    int e = blockIdx.x * blockDim.x + threadIdx.x;
    if (e >= NEDGES) return;
    int s = src[e], d = dst[e];
    int pos = g_row[d] + atomicAdd(&g_fill[d], 1);
    g_col[pos] = s;
    g_nrm[pos] = g_dis[s] * ew[e] * g_dis[d];
}

// ---------------- building blocks ----------------
// padded staging row, stride 36 floats (conflict-friendly: o*36 %32 spans all bank quads)
__device__ __forceinline__ void stage_row(float* row, const float (&v)[12]) {
    float4* q = reinterpret_cast<float4*>(row);
    q[0] = make_float4(0.f, v[0], v[1], v[2]);
    q[1] = make_float4(v[3], v[4], v[5], v[6]);
    q[2] = make_float4(v[7], v[8], v[9], v[10]);
    q[3] = make_float4(v[11], 0.f, 0.f, 0.f);
    q[4] = make_float4(v[0], v[1], v[2], v[3]);
    q[5] = make_float4(v[4], v[5], v[6], v[7]);
    q[6] = make_float4(v[8], v[9], v[10], v[11]);
    q[7] = make_float4(0.f, 0.f, 0.f, 0.f);
}

// gated temporal conv FMA phase: reads staged xs (stride 36), produces r[12]
template <int CI>
__device__ __forceinline__ void conv_fma(const float* xs, const float* __restrict__ wT,
                                         const float* __restrict__ b, int nl, int o,
                                         float (&r)[12]) {
    ull P[6], Q[6];
#pragma unroll
    for (int i = 0; i < 6; i++) { P[i] = 0ull; Q[i] = 0ull; }
    const ulonglong2* ep = reinterpret_cast<const ulonglong2*>(xs) + nl * CI * 9;
    const float4* wv = reinterpret_cast<const float4*>(wT) + o;
#pragma unroll 2
    for (int c = 0; c < CI; c++) {
        ulonglong2 a0 = ep[0], a1 = ep[1], a2 = ep[2], a3 = ep[3];
        ulonglong2 b0 = ep[4], b1 = ep[5], b2 = ep[6];
        ep += 9;
        ull E[8] = {a0.x, a0.y, a1.x, a1.y, a2.x, a2.y, a3.x, a3.y};
        ull O[6] = {b0.x, b0.y, b1.x, b1.y, b2.x, b2.y};
        float4 wp4 = wv[0];
        float4 wq4 = wv[64];
        wv += 128;
        ull w0 = dupr(wp4.x), w1 = dupr(wp4.y), w2 = dupr(wp4.z);
        ull v0 = dupr(wq4.x), v1 = dupr(wq4.y), v2 = dupr(wq4.z);
#pragma unroll
        for (int i = 0; i < 6; i++) {
            FMA2(P[i], w0, E[i]);
            FMA2(P[i], w1, O[i]);
            FMA2(P[i], w2, E[i + 1]);
            FMA2(Q[i], v0, E[i]);
            FMA2(Q[i], v1, O[i]);
            FMA2(Q[i], v2, E[i + 1]);
        }
    }
    float bp = b[o], bq = b[64 + o];
#pragma unroll
    for (int i = 0; i < 6; i++) {
        float p0 = lof(P[i]) + bp, p1 = hif(P[i]) + bp;
        float q0 = lof(Q[i]) + bq, q1 = hif(Q[i]) + bq;
        r[2 * i]     = p0 * (1.0f / (1.0f + __expf(-q0)));
        r[2 * i + 1] = p1 * (1.0f / (1.0f + __expf(-q1)));
    }
}

// channel mix FMA phase: reads sb (stride 20), produces m[12]
__device__ __forceinline__ void mix_fma(const float* sb, const ull* __restrict__ gw,
                                        int nl, int o, float (&m)[12]) {
    ull M[6];
#pragma unroll
    for (int i = 0; i < 6; i++) M[i] = 0ull;
    const ulonglong2* sp = reinterpret_cast<const ulonglong2*>(sb) + nl * 64 * 5;
    const ull* gp = gw + o;
#pragma unroll 4
    for (int c = 0; c < 64; c++) {
        ulonglong2 a0 = sp[0], a1 = sp[1], a2 = sp[2];
        sp += 5;
        ull w = gp[0];
        gp += 64;
        FMA2(M[0], w, a0.x); FMA2(M[1], w, a0.y);
        FMA2(M[2], w, a1.x); FMA2(M[3], w, a1.y);
        FMA2(M[4], w, a2.x); FMA2(M[5], w, a2.y);
    }
#pragma unroll
    for (int i = 0; i < 6; i++) { m[2 * i] = lof(M[i]); m[2 * i + 1] = hif(M[i]); }
}

// GCN gather for one (node, channel) row: v = relu(b + dis^2*x[n] + sum nrm*x[src])
__device__ __forceinline__ void gather_row(const float* __restrict__ xin,
                                           const float* __restrict__ gb,
                                           int n, int o, float (&v)[12]) {
    const float4* xv = reinterpret_cast<const float4*>(xin);
    float bb = gb[o];
    float ds = g_dis[n];
    float sc = ds * ds;
    const float4* sp = xv + (size_t)n * 192 + o * 3;
    float4 a0 = sp[0], a1 = sp[1], a2 = sp[2];
    float4 c0 = make_float4(bb + sc * a0.x, bb + sc * a0.y, bb + sc * a0.z, bb + sc * a0.w);
    float4 c1 = make_float4(bb + sc * a1.x, bb + sc * a1.y, bb + sc * a1.z, bb + sc * a1.w);
    float4 c2 = make_float4(bb + sc * a2.x, bb + sc * a2.y, bb + sc * a2.z, bb + sc * a2.w);
    int e = g_row[n];
    const int re = g_row[n + 1];
    for (; e + 1 < re; e += 2) {
        int s0 = __ldg(&g_col[e]), s1 = __ldg(&g_col[e + 1]);
        float f0 = __ldg(&g_nrm[e]), f1 = __ldg(&g_nrm[e + 1]);
        const float4* u = xv + (size_t)s0 * 192 + o * 3;
        const float4* w = xv + (size_t)s1 * 192 + o * 3;
        float4 u0 = u[0], u1 = u[1], u2 = u[2];
        float4 w0 = w[0], w1 = w[1], w2 = w[2];
        c0.x += f0 * u0.x + f1 * w0.x; c0.y += f0 * u0.y + f1 * w0.y;
        c0.z += f0 * u0.z + f1 * w0.z; c0.w += f0 * u0.w + f1 * w0.w;
        c1.x += f0 * u1.x + f1 * w1.x; c1.y += f0 * u1.y + f1 * w1.y;
        c1.z += f0 * u1.z + f1 * w1.z; c1.w += f0 * u1.w + f1 * w1.w;
        c2.x += f0 * u2.x + f1 * w2.x; c2.y += f0 * u2.y + f1 * w2.y;
        c2.z += f0 * u2.z + f1 * w2.z; c2.w += f0 * u2.w + f1 * w2.w;
    }
    if (e < re) {
        int s0 = __ldg(&g_col[e]);
        float f0 = __ldg(&g_nrm[e]);
        const float4* u = xv + (size_t)s0 * 192 + o * 3;
        float4 u0 = u[0], u1 = u[1], u2 = u[2];
        c0.x += f0 * u0.x; c0.y += f0 * u0.y; c0.z += f0 * u0.z; c0.w += f0 * u0.w;
        c1.x += f0 * u1.x; c1.y += f0 * u1.y; c1.z += f0 * u1.z; c1.w += f0 * u1.w;
        c2.x += f0 * u2.x; c2.y += f0 * u2.y; c2.z += f0 * u2.z; c2.w += f0 * u2.w;
    }
    v[0] = fmaxf(c0.x, 0.f); v[1] = fmaxf(c0.y, 0.f); v[2]  = fmaxf(c0.z, 0.f); v[3]  = fmaxf(c0.w, 0.f);
    v[4] = fmaxf(c1.x, 0.f); v[5] = fmaxf(c1.y, 0.f); v[6]  = fmaxf(c1.z, 0.f); v[7]  = fmaxf(c1.w, 0.f);
    v[8] = fmaxf(c2.x, 0.f); v[9] = fmaxf(c2.y, 0.f); v[10] = fmaxf(c2.z, 0.f); v[11] = fmaxf(c2.w, 0.f);
}

__device__ __forceinline__ void write_out12(float* __restrict__ out, int n, int o,
                                            const float (&m)[12]) {
    float4* op = reinterpret_cast<float4*>(out + ((size_t)n * 64 + o) * 12);
    op[0] = make_float4(m[0], m[1], m[2], m[3]);
    op[1] = make_float4(m[4], m[5], m[6], m[7]);
    op[2] = make_float4(m[8], m[9], m[10], m[11]);
}

// ---------------- stage A: tconv1a (CI=32) + mix1 ----------------
__global__ void __launch_bounds__(256, 2)
k_stageA(const float* __restrict__ x, const float* __restrict__ wT,
         const float* __restrict__ b, const ull* __restrict__ gw,
         float* __restrict__ out) {
    __shared__ __align__(16) float sm[5120];  // xs: 4*32*36=4608; sb alias: 4*64*20=5120
    const int tid = threadIdx.x;
    const int nl = tid >> 6;
    const int o = tid & 63;
    const int n0 = blockIdx.x * 4;
    if (o < 32) {
        const float4* xp = reinterpret_cast<const float4*>(x) + ((size_t)(n0 + nl) * 32 + o) * 3;
        float4 a0 = xp[0], a1 = xp[1], a2 = xp[2];
        float v[12] = {a0.x, a0.y, a0.z, a0.w, a1.x, a1.y, a1.z, a1.w, a2.x, a2.y, a2.z, a2.w};
        stage_row(sm + (nl * 32 + o) * 36, v);
    }
    __syncthreads();
    float r[12];
    conv_fma<32>(sm, wT, b, nl, o, r);
    __syncthreads();
    float4* srow = reinterpret_cast<float4*>(sm + (nl * 64 + o) * 20);
    srow[0] = make_float4(r[0], r[1], r[2], r[3]);
    srow[1] = make_float4(r[4], r[5], r[6], r[7]);
    srow[2] = make_float4(r[8], r[9], r[10], r[11]);
    __syncthreads();
    float m[12];
    mix_fma(sm, gw, nl, o, m);
    write_out12(out, n0 + nl, o, m);
}

// ---------------- stage B: gather1 + tconv1b + tconv2a + mix2 ----------------
__global__ void __launch_bounds__(256, 2)
k_stageB(const float* __restrict__ xin, const float* __restrict__ gb,
         const float* __restrict__ w1, const float* __restrict__ b1,
         const float* __restrict__ w2, const float* __restrict__ b2,
         const ull* __restrict__ gw, float* __restrict__ out) {
    __shared__ __align__(16) float sm[9216];  // xs: 4*64*36=9216; sb alias 5120
    const int tid = threadIdx.x;
    const int nl = tid >> 6;
    const int o = tid & 63;
    const int n0 = blockIdx.x * 4;
    float v[12];
    gather_row(xin, gb, n0 + nl, o, v);
    stage_row(sm + (nl * 64 + o) * 36, v);
    __syncthreads();
    float r[12];
    conv_fma<64>(sm, w1, b1, nl, o, r);
    __syncthreads();
    stage_row(sm + (nl * 64 + o) * 36, r);
    __syncthreads();
    conv_fma<64>(sm, w2, b2, nl, o, r);
    __syncthreads();
    float4* srow = reinterpret_cast<float4*>(sm + (nl * 64 + o) * 20);
    srow[0] = make_float4(r[0], r[1], r[2], r[3]);
    srow[1] = make_float4(r[4], r[5], r[6], r[7]);
    srow[2] = make_float4(r[8], r[9], r[10], r[11]);
    __syncthreads();
    float m[12];
    mix_fma(sm, gw, nl, o, m);
    write_out12(out, n0 + nl, o, m);
}

// ---------------- stage C: gather2 + tconv2b + fin ----------------
__global__ void __launch_bounds__(256, 2)
k_stageC(const float* __restrict__ xin, const float* __restrict__ gb,
         const float* __restrict__ w1, const float* __restrict__ b1,
         const float* __restrict__ fw, const float* __restrict__ fb,
         float* __restrict__ out) {
    __shared__ __align__(16) float sm[9216];
    const int tid = threadIdx.x;
    const int nl = tid >> 6;
    const int o = tid & 63;
    const int n0 = blockIdx.x * 4;
    float v[12];
    gather_row(xin, gb, n0 + nl, o, v);
    stage_row(sm + (nl * 64 + o) * 36, v);
    __syncthreads();
    float r[12];
    conv_fma<64>(sm, w1, b1, nl, o, r);
    __syncthreads();
    float4* srow = reinterpret_cast<float4*>(sm + (nl * 64 + o) * 20);
    srow[0] = make_float4(r[0], r[1], r[2], r[3]);
    srow[1] = make_float4(r[4], r[5], r[6], r[7]);
    srow[2] = make_float4(r[8], r[9], r[10], r[11]);
    __syncthreads();
    // fin: 4 threads per oc, split over channel quarters, shfl reduce
    int sub = tid & 3;
    int oc = (tid >> 2) & 15;
    int ocr = oc < 12 ? oc : 11;
    float acc = 0.0f;
    const float4* wrow = reinterpret_cast<const float4*>(fw + ocr * FEAT + sub * 16 * 12);
#pragma unroll 4
    for (int c = 0; c < 16; c++) {
        const float4* sr = reinterpret_cast<const float4*>(sm + (nl * 64 + sub * 16 + c) * 20);
        float4 a0 = sr[0], a1 = sr[1], a2 = sr[2];
        float4 w0 = wrow[0], w1v = wrow[1], w2 = wrow[2];
        wrow += 3;
        acc += a0.x * w0.x + a0.y * w0.y + a0.z * w0.z + a0.w * w0.w;
        acc += a1.x * w1v.x + a1.y * w1v.y + a1.z * w1v.z + a1.w * w1v.w;
        acc += a2.x * w2.x + a2.y * w2.y + a2.z * w2.z + a2.w * w2.w;
    }
    acc += __shfl_xor_sync(0xffffffffu, acc, 1);
    acc += __shfl_xor_sync(0xffffffffu, acc, 2);
    if (sub == 0 && oc < 12)
        out[(n0 + nl) * 12 + oc] = acc + fb[oc];
}

// ---------------- launch ----------------
extern "C" void kernel_launch(void* const* d_in, const int* in_sizes, int n_in,
                              void* d_out, int out_size) {
    const float* x      = (const float*)d_in[0];
    const int*   ei     = (const int*)d_in[1];
    const int*   src    = ei;
    const int*   dst    = ei + NEDGES;
    const float* ew     = (const float*)d_in[2];
    const float* tc1a_w = (const float*)d_in[3];
    const float* tc1a_b = (const float*)d_in[4];
    const float* gc1_w  = (const float*)d_in[5];
    const float* gc1_b  = (const float*)d_in[6];
    const float* tc1b_w = (const float*)d_in[7];
    const float* tc1b_b = (const float*)d_in[8];
    const float* tc2a_w = (const float*)d_in[9];
    const float* tc2a_b = (const float*)d_in[10];
    const float* gc2_w  = (const float*)d_in[11];
    const float* gc2_b  = (const float*)d_in[12];
    const float* tc2b_w = (const float*)d_in[13];
    const float* tc2b_b = (const float*)d_in[14];
    const float* fin_w  = (const float*)d_in[15];
    const float* fin_b  = (const float*)d_in[16];
    float* out = (float*)d_out;

    float *bA, *bB, *w1a, *w1b, *w2a, *w2b;
    ull *g1, *g2;
    cudaGetSymbolAddress((void**)&bA, g_bufA);
    cudaGetSymbolAddress((void**)&bB, g_bufB);
    cudaGetSymbolAddress((void**)&w1a, g_wt1a);
    cudaGetSymbolAddress((void**)&w1b, g_wt1b);
    cudaGetSymbolAddress((void**)&w2a, g_wt2a);
    cudaGetSymbolAddress((void**)&w2b, g_wt2b);
    cudaGetSymbolAddress((void**)&g1, g_gc1T);
    cudaGetSymbolAddress((void**)&g2, g_gc2T);

    // prep: launches 0..3
    const int PREP_TOT = 12288 + 3 * 24576 + 2 * 4096 + NNODES;
    k_prep<<<(PREP_TOT + 255) / 256, 256>>>(tc1a_w, tc1b_w, tc2a_w, tc2b_w, gc1_w, gc2_w);
    k_deg_acc<<<(NEDGES + 255) / 256, 256>>>(dst, ew);
    k_scan<<<1, 1024>>>();
    k_fill<<<(NEDGES + 255) / 256, 256>>>(src, dst, ew);

    const int NB = NNODES / 4;  // 2500

    // hot pipeline: launches 4..6
    k_stageA<<<NB, 256>>>(x, w1a, tc1a_b, g1, bA);
    k_stageB<<<NB, 256>>>(bA, gc1_b, w1b, tc1b_b, w2a, tc2a_b, g2, bB);
    k_stageC<<<NB, 256>>>(bB, gc2_b, w2b, tc2b_b, fin_w, fin_b, out);
}

// round 8
// speedup vs baseline: 1.4993x; 1.4993x over previous
#include <cuda_runtime.h>

#define NNODES 10000
#define NEDGES 160000
#define CINCH  32
#define H      64
#define T      12
#define OUTC   12
#define KW     3
#define FEAT   (H * T)  // 768

typedef unsigned long long ull;

// ---------------- device scratch (no allocations allowed) ----------------
__device__ float g_bufA[NNODES * FEAT];
__device__ float g_bufB[NNODES * FEAT];
__device__ float g_bufC[NNODES * FEAT];
__device__ float g_dis[NNODES];               // deg accumulator, then rsqrt(deg)
// tconv weights: [c][o(128)][k pad to 4]; pad slot stays 0 (zero-init, never written)
__device__ float g_wt1a[CINCH * 2 * H * 4];
__device__ float g_wt1b[H * 2 * H * 4];
__device__ float g_wt2a[H * 2 * H * 4];
__device__ float g_wt2b[H * 2 * H * 4];
__device__ ull   g_gc1T[H * H];               // dup-packed {w,w}, [c*64 + o]
__device__ ull   g_gc2T[H * H];
// CSR
__device__ int   g_cnt[NNODES];
__device__ int   g_fill[NNODES];
__device__ int   g_row[NNODES + 1];
__device__ int   g_col[NEDGES];
__device__ float g_nrm[NEDGES];

// ---------------- f32x2 helpers ----------------
#define FMA2(a, x, y) asm("fma.rn.f32x2 %0, %1, %2, %0;" : "+l"(a) : "l"(x), "l"(y))
__device__ __forceinline__ float lof(ull v) { return __uint_as_float((unsigned)(v & 0xffffffffull)); }
__device__ __forceinline__ float hif(ull v) { return __uint_as_float((unsigned)(v >> 32)); }
__device__ __forceinline__ ull dupr(float f) {
    ull r;
    asm("mov.b64 %0, {%1, %1};" : "=l"(r) : "f"(f));
    return r;
}
__device__ __forceinline__ ull dup2h(float f) {
    unsigned u = __float_as_uint(f);
    return ((ull)u << 32) | (ull)u;
}

// ---------------- fused prep: weight transposes + gcn transposes + deg init ----------
__device__ __forceinline__ void tw_one(const float* __restrict__ w, float* __restrict__ wT,
                                       int cin, int idx) {
    int o = idx / (cin * KW);
    int r = idx - o * cin * KW;
    int c = r / KW;
    int k = r - c * KW;
    wT[(c * 128 + o) * 4 + k] = w[idx];
}

__global__ void k_prep(const float* __restrict__ w1a, const float* __restrict__ w1b,
                       const float* __restrict__ w2a, const float* __restrict__ w2b,
                       const float* __restrict__ gc1, const float* __restrict__ gc2) {
    int idx = blockIdx.x * blockDim.x + threadIdx.x;
    if (idx < 12288) { tw_one(w1a, g_wt1a, CINCH, idx); return; }
    idx -= 12288;
    if (idx < 24576) { tw_one(w1b, g_wt1b, H, idx); return; }
    idx -= 24576;
    if (idx < 24576) { tw_one(w2a, g_wt2a, H, idx); return; }
    idx -= 24576;
    if (idx < 24576) { tw_one(w2b, g_wt2b, H, idx); return; }
    idx -= 24576;
    if (idx < 4096) { int o = idx / H, c = idx - o * H; g_gc1T[c * H + o] = dup2h(gc1[idx]); return; }
    idx -= 4096;
    if (idx < 4096) { int o = idx / H, c = idx - o * H; g_gc2T[c * H + o] = dup2h(gc2[idx]); return; }
    idx -= 4096;
    if (idx < NNODES) { g_dis[idx] = 1.0f; g_cnt[idx] = 0; }
}

__global__ void k_deg_acc(const int* __restrict__ dst, const float* __restrict__ ew) {
    int e = blockIdx.x * blockDim.x + threadIdx.x;
    if (e < NEDGES) {
        int d = dst[e];
        atomicAdd(&g_dis[d], ew[e]);
        atomicAdd(&g_cnt[d], 1);
    }
}

// rsqrt + single-block exclusive scan (warp-shuffle based)
__global__ void k_scan() {
    __shared__ int wsum[32];
    __shared__ int carry_s;
    int tid = threadIdx.x, lane = tid & 31, wid = tid >> 5;
    for (int i = tid; i < NNODES; i += 1024) g_dis[i] = rsqrtf(g_dis[i]);
    if (tid == 0) carry_s = 0;
    __syncthreads();
    for (int base = 0; base < NNODES; base += 1024) {
        int i = base + tid;
        int v = (i < NNODES) ? g_cnt[i] : 0;
        int s = v;
#pragma unroll
        for (int off = 1; off < 32; off <<= 1) {
            int t = __shfl_up_sync(0xffffffffu, s, off);
            if (lane >= off) s += t;
        }
        if (lane == 31) wsum[wid] = s;
        __syncthreads();
        if (wid == 0) {
            int ws = wsum[lane];
#pragma unroll
            for (int off = 1; off < 32; off <<= 1) {
                int t = __shfl_up_sync(0xffffffffu, ws, off);
                if (lane >= off) ws += t;
            }
            wsum[lane] = ws;
        }
        __syncthreads();
        if (i < NNODES) { g_row[i] = carry_s + (wid ? wsum[wid - 1] : 0) + s - v; g_fill[i] = 0; }
        __syncthreads();
        if (tid == 1023) carry_s += wsum[31];
        __syncthreads();
    }
    if (tid == 0) g_row[NNODES] = carry_s;
}

__global__ void k_fill(const int* __restrict__ src, const int* __restrict__ dst,
                       const float* __restrict__ ew) {
    int e = blockIdx.x * blockDim.x + threadIdx.x;
    if (e >= NEDGES) return;
    int s = src[e], d = dst[e];
    int pos = g_row[d] + atomicAdd(&g_fill[d], 1);
    g_col[pos] = s;
    g_nrm[pos] = g_dis[s] * ew[e] * g_dis[d];
}

// ---------------- tconv core: load x to smem, run gated conv, return r[12] ----------------
// block: 256 threads = 4 nodes x 64 output channels.
// xs row per (n,c): 32 floats = xp[16](pad+x0..11+3pad) then xq[16](x0..11+4pad)
template <int CI>
__device__ __forceinline__ void tconv_core(const float* __restrict__ x,
                                           const float* __restrict__ wT,
                                           const float* __restrict__ b,
                                           float* xs, int tid, int nl, int o, int n0,
                                           float (&r)[12]) {
    for (int idx = tid; idx < 4 * CI * 12; idx += 256) {
        int nn = idx / (CI * 12);
        int rr = idx - nn * (CI * 12);
        int c = rr / 12;
        int t = rr - c * 12;
        float v = x[(n0 + nn) * (CI * 12) + rr];
        float* row = xs + (nn * CI + c) * 32;
        row[t + 1] = v;
        row[16 + t] = v;
    }
    for (int idx = tid; idx < 4 * CI; idx += 256) {
        float* row = xs + idx * 32;
        row[0] = 0.f; row[13] = 0.f; row[14] = 0.f; row[15] = 0.f;
        row[28] = 0.f; row[29] = 0.f; row[30] = 0.f; row[31] = 0.f;
    }
    __syncthreads();

    ull P[6], Q[6];
#pragma unroll
    for (int i = 0; i < 6; i++) { P[i] = 0ull; Q[i] = 0ull; }

    const ulonglong2* ep = reinterpret_cast<const ulonglong2*>(xs) + nl * CI * 8;
    const float4* wv = reinterpret_cast<const float4*>(wT) + o;

#pragma unroll 2
    for (int c = 0; c < CI; c++) {
        ulonglong2 a0 = ep[0], a1 = ep[1], a2 = ep[2], a3 = ep[3];
        ulonglong2 b0 = ep[4], b1 = ep[5], b2 = ep[6];
        ep += 8;
        ull E[8] = {a0.x, a0.y, a1.x, a1.y, a2.x, a2.y, a3.x, a3.y};
        ull O[6] = {b0.x, b0.y, b1.x, b1.y, b2.x, b2.y};
        float4 wp4 = wv[0];       // P taps for this (c,o)
        float4 wq4 = wv[64];      // Q taps
        wv += 128;
        ull w0 = dupr(wp4.x), w1 = dupr(wp4.y), w2 = dupr(wp4.z);
        ull v0 = dupr(wq4.x), v1 = dupr(wq4.y), v2 = dupr(wq4.z);
#pragma unroll
        for (int i = 0; i < 6; i++) {
            FMA2(P[i], w0, E[i]);
            FMA2(P[i], w1, O[i]);
            FMA2(P[i], w2, E[i + 1]);
            FMA2(Q[i], v0, E[i]);
            FMA2(Q[i], v1, O[i]);
            FMA2(Q[i], v2, E[i + 1]);
        }
    }

    float bp = b[o], bq = b[64 + o];
#pragma unroll
    for (int i = 0; i < 6; i++) {
        float p0 = lof(P[i]) + bp, p1 = hif(P[i]) + bp;
        float q0 = lof(Q[i]) + bq, q1 = hif(Q[i]) + bq;
        r[2 * i]     = p0 * (1.0f / (1.0f + __expf(-q0)));
        r[2 * i + 1] = p1 * (1.0f / (1.0f + __expf(-q1)));
    }
}

// ---------------- plain tconv (tconv1b) ----------------
template <int CI>
__global__ void __launch_bounds__(256)
k_tconv(const float* __restrict__ x, const float* __restrict__ wT,
        const float* __restrict__ b, float* __restrict__ out) {
    __shared__ __align__(16) float xs[4 * CI * 32];
    const int tid = threadIdx.x;
    const int nl = tid >> 6;
    const int o = tid & 63;
    const int n0 = blockIdx.x * 4;
    float r[12];
    tconv_core<CI>(x, wT, b, xs, tid, nl, o, n0, r);
    float4* op = reinterpret_cast<float4*>(out + ((n0 + nl) * 64 + o) * 12);
    op[0] = make_float4(r[0], r[1], r[2], r[3]);
    op[1] = make_float4(r[4], r[5], r[6], r[7]);
    op[2] = make_float4(r[8], r[9], r[10], r[11]);
}

// ---------------- tconv + channel mix fused ----------------
template <int CI>
__global__ void __launch_bounds__(256)
k_tconv_mix(const float* __restrict__ x, const float* __restrict__ wT,
            const float* __restrict__ b, const ull* __restrict__ gw,
            float* __restrict__ out) {
    __shared__ __align__(16) float xs[4 * CI * 32];
    __shared__ __align__(16) float sb[4 * 64 * 16];
    const int tid = threadIdx.x;
    const int nl = tid >> 6;
    const int o = tid & 63;
    const int n0 = blockIdx.x * 4;
    float r[12];
    tconv_core<CI>(x, wT, b, xs, tid, nl, o, n0, r);

    float4* srow = reinterpret_cast<float4*>(sb + (nl * 64 + o) * 16);
    srow[0] = make_float4(r[0], r[1], r[2], r[3]);
    srow[1] = make_float4(r[4], r[5], r[6], r[7]);
    srow[2] = make_float4(r[8], r[9], r[10], r[11]);
    __syncthreads();

    ull M[6];
#pragma unroll
    for (int i = 0; i < 6; i++) M[i] = 0ull;
    const ulonglong2* sp = reinterpret_cast<const ulonglong2*>(sb) + nl * 64 * 4;
    const ull* gp = gw + o;
#pragma unroll 4
    for (int c = 0; c < 64; c++) {
        ulonglong2 a0 = sp[0], a1 = sp[1], a2 = sp[2];
        sp += 4;
        ull w = gp[0];
        gp += 64;
        FMA2(M[0], w, a0.x); FMA2(M[1], w, a0.y);
        FMA2(M[2], w, a1.x); FMA2(M[3], w, a1.y);
        FMA2(M[4], w, a2.x); FMA2(M[5], w, a2.y);
    }
    float4* op = reinterpret_cast<float4*>(out + ((n0 + nl) * 64 + o) * 12);
    op[0] = make_float4(lof(M[0]), hif(M[0]), lof(M[1]), hif(M[1]));
    op[1] = make_float4(lof(M[2]), hif(M[2]), lof(M[3]), hif(M[3]));
    op[2] = make_float4(lof(M[4]), hif(M[4]), lof(M[5]), hif(M[5]));
}

// ---------------- tconv + final 1x12 conv fused ----------------
__global__ void __launch_bounds__(256)
k_tconv_fin(const float* __restrict__ x, const float* __restrict__ wT,
            const float* __restrict__ b, const float* __restrict__ fw,
            const float* __restrict__ fb, float* __restrict__ out) {
    __shared__ __align__(16) float xs[4 * H * 32];
    __shared__ __align__(16) float sb[4 * 64 * 16];
    const int tid = threadIdx.x;
    const int nl = tid >> 6;
    const int o = tid & 63;
    const int n0 = blockIdx.x * 4;
    float r[12];
    tconv_core<H>(x, wT, b, xs, tid, nl, o, n0, r);

    float4* srow = reinterpret_cast<float4*>(sb + (nl * 64 + o) * 16);
    srow[0] = make_float4(r[0], r[1], r[2], r[3]);
    srow[1] = make_float4(r[4], r[5], r[6], r[7]);
    srow[2] = make_float4(r[8], r[9], r[10], r[11]);
    __syncthreads();

    // fin: 4 threads per oc, split over channel quarters, shfl reduce.
    int sub = tid & 3;
    int oc = (tid >> 2) & 15;
    int ocr = oc < 12 ? oc : 11;  // clamp to keep reads in-bounds; lanes stay convergent
    float acc = 0.0f;
    const float4* wrow = reinterpret_cast<const float4*>(fw + ocr * FEAT + sub * 16 * 12);
#pragma unroll 4
    for (int c = 0; c < 16; c++) {
        const float4* sr = reinterpret_cast<const float4*>(sb + (nl * 64 + sub * 16 + c) * 16);
        float4 a0 = sr[0], a1 = sr[1], a2 = sr[2];
        float4 w0 = wrow[0], w1v = wrow[1], w2 = wrow[2];
        wrow += 3;
        acc += a0.x * w0.x + a0.y * w0.y + a0.z * w0.z + a0.w * w0.w;
        acc += a1.x * w1v.x + a1.y * w1v.y + a1.z * w1v.z + a1.w * w1v.w;
        acc += a2.x * w2.x + a2.y * w2.y + a2.z * w2.z + a2.w * w2.w;
    }
    acc += __shfl_xor_sync(0xffffffffu, acc, 1);
    acc += __shfl_xor_sync(0xffffffffu, acc, 2);
    if (sub == 0 && oc < 12)
        out[(n0 + nl) * 12 + oc] = acc + fb[oc];
}

// ---------------- GCN gather: out[n] = relu(b + dis[n]^2 * x[n] + sum_e nrm*x[src]) --------
__global__ void __launch_bounds__(192)
k_gather(const float* __restrict__ x, float* __restrict__ out, const float* __restrict__ b) {
    const int n = blockIdx.x;
    const int j = threadIdx.x;  // 0..191 float4 slots
    float bb = b[j / 3];
    float ds = g_dis[n];
    float sc = ds * ds;
    const float4* xv = reinterpret_cast<const float4*>(x);
    float4 v = xv[(size_t)n * 192 + j];
    float4 acc = make_float4(bb + sc * v.x, bb + sc * v.y, bb + sc * v.z, bb + sc * v.w);
    int e = g_row[n];
    const int end = g_row[n + 1];
    for (; e < end; e++) {
        int s = __ldg(&g_col[e]);
        float c = __ldg(&g_nrm[e]);
        float4 u = xv[(size_t)s * 192 + j];
        acc.x += c * u.x; acc.y += c * u.y; acc.z += c * u.z; acc.w += c * u.w;
    }
    reinterpret_cast<float4*>(out)[(size_t)n * 192 + j] =
        make_float4(fmaxf(acc.x, 0.f), fmaxf(acc.y, 0.f), fmaxf(acc.z, 0.f), fmaxf(acc.w, 0.f));
}

// ---------------- launch ----------------
extern "C" void kernel_launch(void* const* d_in, const int* in_sizes, int n_in,
                              void* d_out, int out_size) {
    const float* x      = (const float*)d_in[0];
    const int*   ei     = (const int*)d_in[1];
    const int*   src    = ei;
    const int*   dst    = ei + NEDGES;
    const float* ew     = (const float*)d_in[2];
    const float* tc1a_w = (const float*)d_in[3];
    const float* tc1a_b = (const float*)d_in[4];
    const float* gc1_w  = (const float*)d_in[5];
    const float* gc1_b  = (const float*)d_in[6];
    const float* tc1b_w = (const float*)d_in[7];
    const float* tc1b_b = (const float*)d_in[8];
    const float* tc2a_w = (const float*)d_in[9];
    const float* tc2a_b = (const float*)d_in[10];
    const float* gc2_w  = (const float*)d_in[11];
    const float* gc2_b  = (const float*)d_in[12];
    const float* tc2b_w = (const float*)d_in[13];
    const float* tc2b_b = (const float*)d_in[14];
    const float* fin_w  = (const float*)d_in[15];
    const float* fin_b  = (const float*)d_in[16];
    float* out = (float*)d_out;

    float *bA, *bB, *bC, *w1a, *w1b, *w2a, *w2b;
    ull *g1, *g2;
    cudaGetSymbolAddress((void**)&bA, g_bufA);
    cudaGetSymbolAddress((void**)&bB, g_bufB);
    cudaGetSymbolAddress((void**)&bC, g_bufC);
    cudaGetSymbolAddress((void**)&w1a, g_wt1a);
    cudaGetSymbolAddress((void**)&w1b, g_wt1b);
    cudaGetSymbolAddress((void**)&w2a, g_wt2a);
    cudaGetSymbolAddress((void**)&w2b, g_wt2b);
    cudaGetSymbolAddress((void**)&g1, g_gc1T);
    cudaGetSymbolAddress((void**)&g2, g_gc2T);

    const int NB = NNODES / 4;  // 2500

    // launches 1..3: prep (tconv1a+mix has no CSR dependency, so CSR build happens later)
    const int PREP_TOT = 12288 + 3 * 24576 + 2 * 4096 + NNODES;
    k_prep<<<(PREP_TOT + 255) / 256, 256>>>(tc1a_w, tc1b_w, tc2a_w, tc2b_w, gc1_w, gc2_w);
    k_deg_acc<<<(NEDGES + 255) / 256, 256>>>(dst, ew);
    k_scan<<<1, 1024>>>();

    // launch 4: hot kernel at the ncu capture position
    k_tconv_mix<CINCH><<<NB, 256>>>(x, w1a, tc1a_b, g1, bA);   // tconv1a + mix1

    // CSR fill, then the rest of the pipeline
    k_fill<<<(NEDGES + 255) / 256, 256>>>(src, dst, ew);
    k_gather<<<NNODES, 192>>>(bA, bB, gc1_b);                   // +bias +selfloop +relu
    k_tconv<H><<<NB, 256>>>(bB, w1b, tc1b_b, bC);               // tconv1b
    k_tconv_mix<H><<<NB, 256>>>(bC, w2a, tc2a_b, g2, bA);       // tconv2a + mix2
    k_gather<<<NNODES, 192>>>(bA, bB, gc2_b);
    k_tconv_fin<<<NB, 256>>>(bB, w2b, tc2b_b, fin_w, fin_b, out);  // tconv2b + fin
}

// round 10
// speedup vs baseline: 1.7348x; 1.1571x over previous
#include <cuda_runtime.h>

#define NNODES 10000
#define NEDGES 160000
#define CINCH  32
#define H      64
#define T      12
#define OUTC   12
#define KW     3
#define FEAT   (H * T)  // 768

typedef unsigned long long ull;

// ---------------- device scratch (no allocations allowed) ----------------
__device__ float g_bufA[NNODES * FEAT];
__device__ float g_bufB[NNODES * FEAT];
__device__ float g_bufC[NNODES * FEAT];
__device__ float g_dis[NNODES];               // deg accumulator, then rsqrt(deg)
// tconv weights: [c][o(128)][k pad to 4]; pad slot stays 0 (zero-init, never written)
__device__ float g_wt1a[CINCH * 2 * H * 4];
__device__ float g_wt1b[H * 2 * H * 4];
__device__ float g_wt2a[H * 2 * H * 4];
__device__ float g_wt2b[H * 2 * H * 4];
__device__ ull   g_gc1T[H * H];               // dup-packed {w,w}, [c*64 + o]
__device__ ull   g_gc2T[H * H];
// CSR
__device__ int   g_cnt[NNODES];
__device__ int   g_fill[NNODES];
__device__ int   g_row[NNODES + 1];
__device__ int   g_col[NEDGES];
__device__ float g_nrm[NEDGES];

// ---------------- f32x2 helpers ----------------
#define FMA2(a, x, y) asm("fma.rn.f32x2 %0, %1, %2, %0;" : "+l"(a) : "l"(x), "l"(y))
__device__ __forceinline__ float lof(ull v) { return __uint_as_float((unsigned)(v & 0xffffffffull)); }
__device__ __forceinline__ float hif(ull v) { return __uint_as_float((unsigned)(v >> 32)); }
__device__ __forceinline__ ull dupr(float f) {
    ull r;
    asm("mov.b64 %0, {%1, %1};" : "=l"(r) : "f"(f));
    return r;
}
__device__ __forceinline__ ull dup2h(float f) {
    unsigned u = __float_as_uint(f);
    return ((ull)u << 32) | (ull)u;
}

// ---------------- fused prep: weight transposes + gcn transposes + deg init ----------
__device__ __forceinline__ void tw_one(const float* __restrict__ w, float* __restrict__ wT,
                                       int cin, int idx) {
    int o = idx / (cin * KW);
    int r = idx - o * cin * KW;
    int c = r / KW;
    int k = r - c * KW;
    wT[(c * 128 + o) * 4 + k] = w[idx];
}

__global__ void k_prep(const float* __restrict__ w1a, const float* __restrict__ w1b,
                       const float* __restrict__ w2a, const float* __restrict__ w2b,
                       const float* __restrict__ gc1, const float* __restrict__ gc2) {
    int idx = blockIdx.x * blockDim.x + threadIdx.x;
    if (idx < 12288) { tw_one(w1a, g_wt1a, CINCH, idx); return; }
    idx -= 12288;
    if (idx < 24576) { tw_one(w1b, g_wt1b, H, idx); return; }
    idx -= 24576;
    if (idx < 24576) { tw_one(w2a, g_wt2a, H, idx); return; }
    idx -= 24576;
    if (idx < 24576) { tw_one(w2b, g_wt2b, H, idx); return; }
    idx -= 24576;
    if (idx < 4096) { int o = idx / H, c = idx - o * H; g_gc1T[c * H + o] = dup2h(gc1[idx]); return; }
    idx -= 4096;
    if (idx < 4096) { int o = idx / H, c = idx - o * H; g_gc2T[c * H + o] = dup2h(gc2[idx]); return; }
    idx -= 4096;
    if (idx < NNODES) { g_dis[idx] = 1.0f; g_cnt[idx] = 0; }
}

__global__ void k_deg_acc(const int* __restrict__ dst, const float* __restrict__ ew) {
    int e = blockIdx.x * blockDim.x + threadIdx.x;
    if (e < NEDGES) {
        int d = dst[e];
        atomicAdd(&g_dis[d], ew[e]);
        atomicAdd(&g_cnt[d], 1);
    }
}

// rsqrt + single-block exclusive scan (warp-shuffle based)
__global__ void k_scan() {
    __shared__ int wsum[32];
    __shared__ int carry_s;
    int tid = threadIdx.x, lane = tid & 31, wid = tid >> 5;
    for (int i = tid; i < NNODES; i += 1024) g_dis[i] = rsqrtf(g_dis[i]);
    if (tid == 0) carry_s = 0;
    __syncthreads();
    for (int base = 0; base < NNODES; base += 1024) {
        int i = base + tid;
        int v = (i < NNODES) ? g_cnt[i] : 0;
        int s = v;
#pragma unroll
        for (int off = 1; off < 32; off <<= 1) {
            int t = __shfl_up_sync(0xffffffffu, s, off);
            if (lane >= off) s += t;
        }
        if (lane == 31) wsum[wid] = s;
        __syncthreads();
        if (wid == 0) {
            int ws = wsum[lane];
#pragma unroll
            for (int off = 1; off < 32; off <<= 1) {
                int t = __shfl_up_sync(0xffffffffu, ws, off);
                if (lane >= off) ws += t;
            }
            wsum[lane] = ws;
        }
        __syncthreads();
        if (i < NNODES) { g_row[i] = carry_s + (wid ? wsum[wid - 1] : 0) + s - v; g_fill[i] = 0; }
        __syncthreads();
        if (tid == 1023) carry_s += wsum[31];
        __syncthreads();
    }
    if (tid == 0) g_row[NNODES] = carry_s;
}

__global__ void k_fill(const int* __restrict__ src, const int* __restrict__ dst,
                       const float* __restrict__ ew) {
    int e = blockIdx.x * blockDim.x + threadIdx.x;
    if (e >= NEDGES) return;
    int s = src[e], d = dst[e];
    int pos = g_row[d] + atomicAdd(&g_fill[d], 1);
    g_col[pos] = s;
    g_nrm[pos] = g_dis[s] * ew[e] * g_dis[d];
}

// ---------------- tconv core, 2 nodes per thread ----------------
// block: 128 threads = 64 o-channels x 2 node-pairs -> 4 nodes/block.
// xs row per (n,c): 36 floats: xp[0..15] = [0, x0..x11, 0,0,0]; xq[16..27] = [x0..x11]; pad.
template <int CI>
__device__ __forceinline__ void tconv2_core(const float* __restrict__ x,
                                            const float* __restrict__ wT,
                                            const float* __restrict__ b,
                                            float* xs, int tid, int g, int o, int n0,
                                            float (&rA)[12], float (&rB)[12]) {
    for (int idx = tid; idx < 4 * CI * 12; idx += 128) {
        int nn = idx / (CI * 12);
        int rr = idx - nn * (CI * 12);
        int c = rr / 12;
        int t = rr - c * 12;
        float v = x[(n0 + nn) * (CI * 12) + rr];
        float* row = xs + (nn * CI + c) * 36;
        row[t + 1] = v;
        row[16 + t] = v;
    }
    for (int idx = tid; idx < 4 * CI; idx += 128) {
        float* row = xs + idx * 36;
        row[0] = 0.f; row[13] = 0.f; row[14] = 0.f; row[15] = 0.f;
        row[28] = 0.f; row[29] = 0.f; row[30] = 0.f; row[31] = 0.f;
    }
    __syncthreads();

    ull PA[6], QA[6], PB[6], QB[6];
#pragma unroll
    for (int i = 0; i < 6; i++) { PA[i] = 0ull; QA[i] = 0ull; PB[i] = 0ull; QB[i] = 0ull; }

    const ulonglong2* epA = reinterpret_cast<const ulonglong2*>(xs) + (2 * g) * CI * 9;
    const ulonglong2* epB = epA + CI * 9;
    const float4* wv = reinterpret_cast<const float4*>(wT) + o;

#pragma unroll 2
    for (int c = 0; c < CI; c++) {
        float4 wp4 = wv[0];   // P taps for this (c,o)
        float4 wq4 = wv[64];  // Q taps
        wv += 128;
        ull w0 = dupr(wp4.x), w1 = dupr(wp4.y), w2 = dupr(wp4.z);
        ull v0 = dupr(wq4.x), v1 = dupr(wq4.y), v2 = dupr(wq4.z);
        {
            ulonglong2 a0 = epA[0], a1 = epA[1], a2 = epA[2], a3 = epA[3];
            ulonglong2 b0 = epA[4], b1 = epA[5], b2 = epA[6];
            epA += 9;
            ull E[8] = {a0.x, a0.y, a1.x, a1.y, a2.x, a2.y, a3.x, a3.y};
            ull O[6] = {b0.x, b0.y, b1.x, b1.y, b2.x, b2.y};
#pragma unroll
            for (int i = 0; i < 6; i++) {
                FMA2(PA[i], w0, E[i]);
                FMA2(PA[i], w1, O[i]);
                FMA2(PA[i], w2, E[i + 1]);
                FMA2(QA[i], v0, E[i]);
                FMA2(QA[i], v1, O[i]);
                FMA2(QA[i], v2, E[i + 1]);
            }
        }
        {
            ulonglong2 a0 = epB[0], a1 = epB[1], a2 = epB[2], a3 = epB[3];
            ulonglong2 b0 = epB[4], b1 = epB[5], b2 = epB[6];
            epB += 9;
            ull E[8] = {a0.x, a0.y, a1.x, a1.y, a2.x, a2.y, a3.x, a3.y};
            ull O[6] = {b0.x, b0.y, b1.x, b1.y, b2.x, b2.y};
#pragma unroll
            for (int i = 0; i < 6; i++) {
                FMA2(PB[i], w0, E[i]);
                FMA2(PB[i], w1, O[i]);
                FMA2(PB[i], w2, E[i + 1]);
                FMA2(QB[i], v0, E[i]);
                FMA2(QB[i], v1, O[i]);
                FMA2(QB[i], v2, E[i + 1]);
            }
        }
    }

    float bp = b[o], bq = b[64 + o];
#pragma unroll
    for (int i = 0; i < 6; i++) {
        float p0 = lof(PA[i]) + bp, p1 = hif(PA[i]) + bp;
        float q0 = lof(QA[i]) + bq, q1 = hif(QA[i]) + bq;
        rA[2 * i]     = p0 * (1.0f / (1.0f + __expf(-q0)));
        rA[2 * i + 1] = p1 * (1.0f / (1.0f + __expf(-q1)));
        p0 = lof(PB[i]) + bp; p1 = hif(PB[i]) + bp;
        q0 = lof(QB[i]) + bq; q1 = hif(QB[i]) + bq;
        rB[2 * i]     = p0 * (1.0f / (1.0f + __expf(-q0)));
        rB[2 * i + 1] = p1 * (1.0f / (1.0f + __expf(-q1)));
    }
}

__device__ __forceinline__ void write12(float* __restrict__ out, int n, int o,
                                        const float (&m)[12]) {
    float4* op = reinterpret_cast<float4*>(out + ((size_t)n * 64 + o) * 12);
    op[0] = make_float4(m[0], m[1], m[2], m[3]);
    op[1] = make_float4(m[4], m[5], m[6], m[7]);
    op[2] = make_float4(m[8], m[9], m[10], m[11]);
}

__device__ __forceinline__ void sb_stage(float* sb, int node_l, int o, const float (&m)[12]) {
    float4* q = reinterpret_cast<float4*>(sb + (node_l * 64 + o) * 20);
    q[0] = make_float4(m[0], m[1], m[2], m[3]);
    q[1] = make_float4(m[4], m[5], m[6], m[7]);
    q[2] = make_float4(m[8], m[9], m[10], m[11]);
}

// ---------------- plain tconv (tconv1b) ----------------
template <int CI>
__global__ void __launch_bounds__(128, 4)
k_tconv2(const float* __restrict__ x, const float* __restrict__ wT,
         const float* __restrict__ b, float* __restrict__ out) {
    __shared__ __align__(16) float xs[4 * CI * 36];
    const int tid = threadIdx.x;
    const int g = tid >> 6;
    const int o = tid & 63;
    const int n0 = blockIdx.x * 4;
    float rA[12], rB[12];
    tconv2_core<CI>(x, wT, b, xs, tid, g, o, n0, rA, rB);
    write12(out, n0 + 2 * g, o, rA);
    write12(out, n0 + 2 * g + 1, o, rB);
}

// ---------------- tconv + channel mix fused ----------------
template <int CI>
__global__ void __launch_bounds__(128, 4)
k_tconv2_mix(const float* __restrict__ x, const float* __restrict__ wT,
             const float* __restrict__ b, const ull* __restrict__ gw,
             float* __restrict__ out) {
    constexpr int XS = 4 * CI * 36;
    constexpr int SB = 4 * 64 * 20;  // 5120
    __shared__ __align__(16) float sm[XS > SB ? XS : SB];
    const int tid = threadIdx.x;
    const int g = tid >> 6;
    const int o = tid & 63;
    const int n0 = blockIdx.x * 4;
    float rA[12], rB[12];
    tconv2_core<CI>(x, wT, b, sm, tid, g, o, n0, rA, rB);

    __syncthreads();  // conv reads of sm done; reuse as sb
    sb_stage(sm, 2 * g, o, rA);
    sb_stage(sm, 2 * g + 1, o, rB);
    __syncthreads();

    ull MA[6], MB[6];
#pragma unroll
    for (int i = 0; i < 6; i++) { MA[i] = 0ull; MB[i] = 0ull; }
    const ulonglong2* spA = reinterpret_cast<const ulonglong2*>(sm) + (2 * g) * 64 * 5;
    const ulonglong2* spB = spA + 64 * 5;
    const ull* gp = gw + o;
#pragma unroll 2
    for (int c = 0; c < 64; c++) {
        ull w = gp[0];
        gp += 64;
        ulonglong2 a0 = spA[0], a1 = spA[1], a2 = spA[2];
        spA += 5;
        FMA2(MA[0], w, a0.x); FMA2(MA[1], w, a0.y);
        FMA2(MA[2], w, a1.x); FMA2(MA[3], w, a1.y);
        FMA2(MA[4], w, a2.x); FMA2(MA[5], w, a2.y);
        ulonglong2 c0 = spB[0], c1 = spB[1], c2 = spB[2];
        spB += 5;
        FMA2(MB[0], w, c0.x); FMA2(MB[1], w, c0.y);
        FMA2(MB[2], w, c1.x); FMA2(MB[3], w, c1.y);
        FMA2(MB[4], w, c2.x); FMA2(MB[5], w, c2.y);
    }
    float mA[12], mB[12];
#pragma unroll
    for (int i = 0; i < 6; i++) {
        mA[2 * i] = lof(MA[i]); mA[2 * i + 1] = hif(MA[i]);
        mB[2 * i] = lof(MB[i]); mB[2 * i + 1] = hif(MB[i]);
    }
    write12(out, n0 + 2 * g, o, mA);
    write12(out, n0 + 2 * g + 1, o, mB);
}

// ---------------- tconv + final 1x12 conv fused ----------------
__global__ void __launch_bounds__(128, 4)
k_tconv2_fin(const float* __restrict__ x, const float* __restrict__ wT,
             const float* __restrict__ b, const float* __restrict__ fw,
             const float* __restrict__ fb, float* __restrict__ out) {
    constexpr int XS = 4 * H * 36;   // 9216
    __shared__ __align__(16) float sm[XS];
    const int tid = threadIdx.x;
    const int g = tid >> 6;
    const int o = tid & 63;
    const int n0 = blockIdx.x * 4;
    float rA[12], rB[12];
    tconv2_core<H>(x, wT, b, sm, tid, g, o, n0, rA, rB);

    __syncthreads();
    sb_stage(sm, 2 * g, o, rA);
    sb_stage(sm, 2 * g + 1, o, rB);
    __syncthreads();

    // fin: 96 threads: nl(0..3) x oc(0..11) x half(0..1); dot over 32 c x 12 t; shfl add.
    if (tid < 96) {
        int nl = tid / 24;
        int rr = tid - nl * 24;
        int oc = rr >> 1;
        int s2 = rr & 1;
        const float* gS = sm + nl * 64 * 20 + s2 * 32 * 20;
        const float4* wrow = reinterpret_cast<const float4*>(fw + oc * FEAT + s2 * 32 * 12);
        float acc = 0.0f;
#pragma unroll 4
        for (int c = 0; c < 32; c++) {
            const float4* sr = reinterpret_cast<const float4*>(gS + c * 20);
            float4 a0 = sr[0], a1 = sr[1], a2 = sr[2];
            float4 w0 = wrow[0], w1v = wrow[1], w2 = wrow[2];
            wrow += 3;
            acc += a0.x * w0.x + a0.y * w0.y + a0.z * w0.z + a0.w * w0.w;
            acc += a1.x * w1v.x + a1.y * w1v.y + a1.z * w1v.z + a1.w * w1v.w;
            acc += a2.x * w2.x + a2.y * w2.y + a2.z * w2.z + a2.w * w2.w;
        }
        acc += __shfl_xor_sync(0xffffffffu, acc, 1);
        if (s2 == 0) out[(n0 + nl) * 12 + oc] = acc + fb[oc];
    }
}

// ---------------- GCN gather: out[n] = relu(b + dis[n]^2 * x[n] + sum_e nrm*x[src]) --------
__global__ void __launch_bounds__(192)
k_gather(const float* __restrict__ x, float* __restrict__ out, const float* __restrict__ b) {
    const int n = blockIdx.x;
    const int j = threadIdx.x;  // 0..191 float4 slots
    float bb = b[j / 3];
    float ds = g_dis[n];
    float sc = ds * ds;
    const float4* xv = reinterpret_cast<const float4*>(x);
    float4 v = xv[(size_t)n * 192 + j];
    float4 acc = make_float4(bb + sc * v.x, bb + sc * v.y, bb + sc * v.z, bb + sc * v.w);
    int e = g_row[n];
    const int end = g_row[n + 1];
    for (; e < end; e++) {
        int s = __ldg(&g_col[e]);
        float c = __ldg(&g_nrm[e]);
        float4 u = xv[(size_t)s * 192 + j];
        acc.x += c * u.x; acc.y += c * u.y; acc.z += c * u.z; acc.w += c * u.w;
    }
    reinterpret_cast<float4*>(out)[(size_t)n * 192 + j] =
        make_float4(fmaxf(acc.x, 0.f), fmaxf(acc.y, 0.f), fmaxf(acc.z, 0.f), fmaxf(acc.w, 0.f));
}

// ---------------- launch ----------------
extern "C" void kernel_launch(void* const* d_in, const int* in_sizes, int n_in,
                              void* d_out, int out_size) {
    const float* x      = (const float*)d_in[0];
    const int*   ei     = (const int*)d_in[1];
    const int*   src    = ei;
    const int*   dst    = ei + NEDGES;
    const float* ew     = (const float*)d_in[2];
    const float* tc1a_w = (const float*)d_in[3];
    const float* tc1a_b = (const float*)d_in[4];
    const float* gc1_w  = (const float*)d_in[5];
    const float* gc1_b  = (const float*)d_in[6];
    const float* tc1b_w = (const float*)d_in[7];
    const float* tc1b_b = (const float*)d_in[8];
    const float* tc2a_w = (const float*)d_in[9];
    const float* tc2a_b = (const float*)d_in[10];
    const float* gc2_w  = (const float*)d_in[11];
    const float* gc2_b  = (const float*)d_in[12];
    const float* tc2b_w = (const float*)d_in[13];
    const float* tc2b_b = (const float*)d_in[14];
    const float* fin_w  = (const float*)d_in[15];
    const float* fin_b  = (const float*)d_in[16];
    float* out = (float*)d_out;

    float *bA, *bB, *bC, *w1a, *w1b, *w2a, *w2b;
    ull *g1, *g2;
    cudaGetSymbolAddress((void**)&bA, g_bufA);
    cudaGetSymbolAddress((void**)&bB, g_bufB);
    cudaGetSymbolAddress((void**)&bC, g_bufC);
    cudaGetSymbolAddress((void**)&w1a, g_wt1a);
    cudaGetSymbolAddress((void**)&w1b, g_wt1b);
    cudaGetSymbolAddress((void**)&w2a, g_wt2a);
    cudaGetSymbolAddress((void**)&w2b, g_wt2b);
    cudaGetSymbolAddress((void**)&g1, g_gc1T);
    cudaGetSymbolAddress((void**)&g2, g_gc2T);

    const int NB = NNODES / 4;  // 2500

    // launches 1..3: prep (tconv1a+mix has no CSR dependency; CSR build happens later)
    const int PREP_TOT = 12288 + 3 * 24576 + 2 * 4096 + NNODES;
    k_prep<<<(PREP_TOT + 255) / 256, 256>>>(tc1a_w, tc1b_w, tc2a_w, tc2b_w, gc1_w, gc2_w);
    k_deg_acc<<<(NEDGES + 255) / 256, 256>>>(dst, ew);
    k_scan<<<1, 1024>>>();

    // launch 4: hot kernel at the ncu capture position
    k_tconv2_mix<CINCH><<<NB, 128>>>(x, w1a, tc1a_b, g1, bA);   // tconv1a + mix1

    // CSR fill, then the rest of the pipeline
    k_fill<<<(NEDGES + 255) / 256, 256>>>(src, dst, ew);
    k_gather<<<NNODES, 192>>>(bA, bB, gc1_b);                    // +bias +selfloop +relu
    k_tconv2<H><<<NB, 128>>>(bB, w1b, tc1b_b, bC);               // tconv1b
    k_tconv2_mix<H><<<NB, 128>>>(bC, w2a, tc2a_b, g2, bA);       // tconv2a + mix2
    k_gather<<<NNODES, 192>>>(bA, bB, gc2_b);
    k_tconv2_fin<<<NB, 128>>>(bB, w2b, tc2b_b, fin_w, fin_b, out);  // tconv2b + fin
}